// round 15
// baseline (speedup 1.0000x reference)
#include <cuda_runtime.h>
#include <cuda_fp16.h>

// Problem constants
#define Bsz 2
#define E 2048
#define C 512
#define H 8
#define D 64
#define M_TOT (Bsz * E)       // 4096
#define CAP 320               // per-row nnz capacity (mean ~102)
#define QC 1536               // fused q|k|v half row length

// ---------------- scratch (device globals; no allocation) ----------------
__device__ __half  g_x16[M_TOT * C];        // x in fp16
__device__ __half  g_w16[4 * C * C];        // Wq|Wk|Wv|Wp in fp16
__device__ __half  g_qkv16[M_TOT * QC];     // [row][ q | k | v ] fp16
__device__ __half  g_part0[M_TOT * C];      // attention partial 0 (fp16)
__device__ __half  g_part1[M_TOT * C];      // attention partial 1 (fp16)
__device__ float   g_p[M_TOT * C];          // proj k-half 0 partial (fp32)
__device__ float   g_p2[M_TOT * C];         // proj k-half 1 partial (fp32)
__device__ int     g_cnt[E];
__device__ float2  g_pair[E * CAP];         // (rowoffset-as-bits, maskval)
__device__ float   g_vsum[Bsz * C];

// ---------------- fused: fp32->fp16 conversion + mask CSR + vsum zero -----
// Blocks [0, NCONV): convert x and the 4 weight matrices to fp16.
// Blocks [NCONV, NCONV + E/8): mask -> per-row (rowoff,val) pair lists,
// warp per row (8 rows per 256-thread block), ballot compaction.
#define NCONV ((M_TOT * C + 4 * C * C) / 4 / 256)   // 3072

__global__ __launch_bounds__(256) void conv_and_csr(
    const float* __restrict__ x,
    const float* __restrict__ Wq, const float* __restrict__ Wk,
    const float* __restrict__ Wv, const float* __restrict__ Wp,
    const float* __restrict__ mask)
{
    if (blockIdx.x < NCONV) {
        if (blockIdx.x == 0) {   // also zero the vsum accumulator (1024 floats)
            *reinterpret_cast<float4*>(g_vsum + threadIdx.x * 4) =
                make_float4(0.f, 0.f, 0.f, 0.f);
        }
        int idx = (blockIdx.x * 256 + threadIdx.x) * 4;   // float4 granularity
        const int NX = M_TOT * C;                          // 2^21
        const float* src;
        __half* dst;
        if (idx < NX) {
            src = x + idx;
            dst = g_x16 + idx;
        } else {
            int j = idx - NX;                              // [0, 2^20)
            int region = j >> 18;
            int off = j & ((C * C) - 1);
            src = (region == 0 ? Wq : region == 1 ? Wk : region == 2 ? Wv : Wp) + off;
            dst = g_w16 + j;
        }
        float4 f = *reinterpret_cast<const float4*>(src);
        *reinterpret_cast<__half2*>(dst)     = __floats2half2_rn(f.x, f.y);
        *reinterpret_cast<__half2*>(dst + 2) = __floats2half2_rn(f.z, f.w);
        return;
    }

    // ---- CSR part: warp per row ----
    int row  = (blockIdx.x - NCONV) * 8 + (threadIdx.x >> 5);
    int lane = threadIdx.x & 31;

    int cnt = 0;
    const float* mrow = mask + (size_t)row * E;
    float2* prow = g_pair + row * CAP;
    unsigned below = (1u << lane) - 1u;

    float4 v = *reinterpret_cast<const float4*>(mrow + lane * 4);
    for (int j0 = 0; j0 < E; j0 += 128) {
        float4 nv;
        if (j0 + 128 < E)
            nv = *reinterpret_cast<const float4*>(mrow + j0 + 128 + lane * 4);

        unsigned b0 = __ballot_sync(0xFFFFFFFFu, v.x != 0.0f);
        unsigned b1 = __ballot_sync(0xFFFFFFFFu, v.y != 0.0f);
        unsigned b2 = __ballot_sync(0xFFFFFFFFu, v.z != 0.0f);
        unsigned b3 = __ballot_sync(0xFFFFFFFFu, v.w != 0.0f);
        int t0 = __popc(b0), t1 = __popc(b1), t2 = __popc(b2), t3 = __popc(b3);
        int jb = (j0 + lane * 4) * QC;

        if (v.x != 0.0f) {
            int o = cnt + __popc(b0 & below);
            if (o < CAP) prow[o] = make_float2(__int_as_float(jb), v.x);
        }
        if (v.y != 0.0f) {
            int o = cnt + t0 + __popc(b1 & below);
            if (o < CAP) prow[o] = make_float2(__int_as_float(jb + QC), v.y);
        }
        if (v.z != 0.0f) {
            int o = cnt + t0 + t1 + __popc(b2 & below);
            if (o < CAP) prow[o] = make_float2(__int_as_float(jb + 2 * QC), v.z);
        }
        if (v.w != 0.0f) {
            int o = cnt + t0 + t1 + t2 + __popc(b3 & below);
            if (o < CAP) prow[o] = make_float2(__int_as_float(jb + 3 * QC), v.w);
        }
        cnt += t0 + t1 + t2 + t3;
        v = nv;
    }
    if (lane == 0) g_cnt[row] = (cnt > CAP) ? CAP : cnt;
}

// =============== fp16 tensor-core GEMM (ldmatrix frag loads) ==============
// C[m, coloff+n] = sum_k A[m,k]*B[n,k].  128x128x32 tiles, double-buffered,
// 256 threads = 8 warps (2m x 4n), warp tile 64x32, mma m16n8k16 f16->f32.
// ADD_A: A operand = half-sum of A and A2 (attention partials combiner).
// KSPLIT>1: blockIdx.z selects a k-range [z*C/KSPLIT, ...) and an output
// partial buffer (Cout + z*M_TOT*C floats); B is B0 for all z.
// KSPLIT==1 QKV path: z selects B0/B1/B2 + column offset; z==2 (v-slice)
// folds per-column sums into g_vsum.
#define GM 128
#define GN 128
#define GKH 32     // k-halves per tile
#define SAH 40     // padded row stride in halves (80B -> conflict-free LDSM)

__device__ __forceinline__ void mma_f16(float* c, const unsigned* a, const unsigned* b) {
    asm volatile(
        "mma.sync.aligned.m16n8k16.row.col.f32.f16.f16.f32 "
        "{%0,%1,%2,%3}, {%4,%5,%6,%7}, {%8,%9}, {%0,%1,%2,%3};\n"
        : "+f"(c[0]), "+f"(c[1]), "+f"(c[2]), "+f"(c[3])
        : "r"(a[0]), "r"(a[1]), "r"(a[2]), "r"(a[3]), "r"(b[0]), "r"(b[1]));
}

__device__ __forceinline__ void ldsm_x4(unsigned* r, const __half* p) {
    unsigned a = (unsigned)__cvta_generic_to_shared(p);
    asm volatile(
        "ldmatrix.sync.aligned.m8n8.x4.shared.b16 {%0,%1,%2,%3}, [%4];\n"
        : "=r"(r[0]), "=r"(r[1]), "=r"(r[2]), "=r"(r[3]) : "r"(a));
}

__device__ __forceinline__ uint4 hadd8(uint4 a, uint4 b) {
    uint4 r;
    *reinterpret_cast<__half2*>(&r.x) = __hadd2(
        *reinterpret_cast<__half2*>(&a.x), *reinterpret_cast<__half2*>(&b.x));
    *reinterpret_cast<__half2*>(&r.y) = __hadd2(
        *reinterpret_cast<__half2*>(&a.y), *reinterpret_cast<__half2*>(&b.y));
    *reinterpret_cast<__half2*>(&r.z) = __hadd2(
        *reinterpret_cast<__half2*>(&a.z), *reinterpret_cast<__half2*>(&b.z));
    *reinterpret_cast<__half2*>(&r.w) = __hadd2(
        *reinterpret_cast<__half2*>(&a.w), *reinterpret_cast<__half2*>(&b.w));
    return r;
}

template <bool HALF_OUT, bool ADD_A, int KSPLIT>
__global__ __launch_bounds__(256) void gemm_f16(
    const __half* __restrict__ A, const __half* __restrict__ A2,
    const __half* __restrict__ B0, const __half* __restrict__ B1,
    const __half* __restrict__ B2,
    void* __restrict__ Cout, int ldc, int coloff_mul)
{
    int z = blockIdx.z;
    const __half* Bm = (KSPLIT > 1) ? B0 : ((z == 0) ? B0 : (z == 1 ? B1 : B2));
    int coloff = (KSPLIT > 1) ? 0 : z * coloff_mul;
    int koff   = (KSPLIT > 1) ? z * (C / KSPLIT) : 0;
    bool dovs = (KSPLIT == 1) && (coloff_mul != 0) && (z == 2);

    __shared__ __align__(16) __half As[2][GM][SAH];
    __shared__ __align__(16) __half Bs[2][GN][SAH];

    int tid  = threadIdx.x;
    int lane = tid & 31;
    int warp = tid >> 5;
    int m0 = blockIdx.y * GM;
    int n0 = blockIdx.x * GN;

    int lr = tid >> 1;
    int lc = (tid & 1) * 16;
    size_t aoff = (size_t)(m0 + lr) * C + lc + koff;
    const __half* Ag  = A + aoff;
    const __half* Ag2 = ADD_A ? (A2 + aoff) : nullptr;
    const __half* Bg  = Bm + (size_t)(n0 + lr) * C + lc + koff;

    int m_base = (warp >> 2) * 64;
    int n_base = (warp & 3) * 32;
    int lrow = lane >> 2;
    int lcol = lane & 3;

    // ldmatrix per-lane row/col components
    int a_row = m_base + (lane & 15);        // + mi*16
    int a_k   = (lane >> 4) * 8;             // + ks*16
    int b_row = n_base + (lane >> 4) * 8 + (lane & 7);   // + nip*16
    int b_k   = ((lane >> 3) & 1) * 8;       // + ks*16

    float acc[4][4][4];
    #pragma unroll
    for (int mi = 0; mi < 4; mi++)
        #pragma unroll
        for (int ni = 0; ni < 4; ni++)
            #pragma unroll
            for (int r = 0; r < 4; r++) acc[mi][ni][r] = 0.0f;

    const int nt = C / GKH / KSPLIT;   // 16 (KSPLIT=1) or 8 (KSPLIT=2)

    uint4 pa0, pa1, pb0, pb1;
    pa0 = *reinterpret_cast<const uint4*>(Ag);
    pa1 = *reinterpret_cast<const uint4*>(Ag + 8);
    if (ADD_A) {
        pa0 = hadd8(pa0, *reinterpret_cast<const uint4*>(Ag2));
        pa1 = hadd8(pa1, *reinterpret_cast<const uint4*>(Ag2 + 8));
    }
    pb0 = *reinterpret_cast<const uint4*>(Bg);
    pb1 = *reinterpret_cast<const uint4*>(Bg + 8);

    *reinterpret_cast<uint4*>(&As[0][lr][lc])     = pa0;
    *reinterpret_cast<uint4*>(&As[0][lr][lc + 8]) = pa1;
    *reinterpret_cast<uint4*>(&Bs[0][lr][lc])     = pb0;
    *reinterpret_cast<uint4*>(&Bs[0][lr][lc + 8]) = pb1;
    __syncthreads();

    for (int kt = 0; kt < nt; kt++) {
        int cur = kt & 1;
        bool more = (kt + 1) < nt;
        if (more) {
            const __half* Ap = Ag + (kt + 1) * GKH;
            const __half* Bp = Bg + (kt + 1) * GKH;
            pa0 = *reinterpret_cast<const uint4*>(Ap);
            pa1 = *reinterpret_cast<const uint4*>(Ap + 8);
            if (ADD_A) {
                const __half* Ap2 = Ag2 + (kt + 1) * GKH;
                pa0 = hadd8(pa0, *reinterpret_cast<const uint4*>(Ap2));
                pa1 = hadd8(pa1, *reinterpret_cast<const uint4*>(Ap2 + 8));
            }
            pb0 = *reinterpret_cast<const uint4*>(Bp);
            pb1 = *reinterpret_cast<const uint4*>(Bp + 8);
        }

        #pragma unroll
        for (int ks = 0; ks < 2; ks++) {
            unsigned afr[4][4];
            #pragma unroll
            for (int mi = 0; mi < 4; mi++)
                ldsm_x4(afr[mi], &As[cur][a_row + mi * 16][ks * 16 + a_k]);
            unsigned bfr[4][2];
            #pragma unroll
            for (int nip = 0; nip < 2; nip++) {
                unsigned t[4];
                ldsm_x4(t, &Bs[cur][b_row + nip * 16][ks * 16 + b_k]);
                bfr[nip * 2][0]     = t[0];
                bfr[nip * 2][1]     = t[1];
                bfr[nip * 2 + 1][0] = t[2];
                bfr[nip * 2 + 1][1] = t[3];
            }
            #pragma unroll
            for (int mi = 0; mi < 4; mi++)
                #pragma unroll
                for (int ni = 0; ni < 4; ni++)
                    mma_f16(acc[mi][ni], afr[mi], bfr[ni]);
        }

        if (more) {
            int nxt = cur ^ 1;
            *reinterpret_cast<uint4*>(&As[nxt][lr][lc])     = pa0;
            *reinterpret_cast<uint4*>(&As[nxt][lr][lc + 8]) = pa1;
            *reinterpret_cast<uint4*>(&Bs[nxt][lr][lc])     = pb0;
            *reinterpret_cast<uint4*>(&Bs[nxt][lr][lc + 8]) = pb1;
            __syncthreads();
        }
    }

    float* Cf = (float*)Cout + ((KSPLIT > 1) ? (size_t)z * M_TOT * C : 0);
    #pragma unroll
    for (int mi = 0; mi < 4; mi++) {
        #pragma unroll
        for (int ni = 0; ni < 4; ni++) {
            int r  = m0 + m_base + mi * 16 + lrow;
            int cc = coloff + n0 + n_base + ni * 8 + lcol * 2;
            if (HALF_OUT) {
                __half* Ch = (__half*)Cout;
                *reinterpret_cast<__half2*>(Ch + (size_t)r * ldc + cc) =
                    __floats2half2_rn(acc[mi][ni][0], acc[mi][ni][1]);
                *reinterpret_cast<__half2*>(Ch + (size_t)(r + 8) * ldc + cc) =
                    __floats2half2_rn(acc[mi][ni][2], acc[mi][ni][3]);
            } else {
                *reinterpret_cast<float2*>(Cf + (size_t)r * ldc + cc) =
                    make_float2(acc[mi][ni][0], acc[mi][ni][1]);
                *reinterpret_cast<float2*>(Cf + (size_t)(r + 8) * ldc + cc) =
                    make_float2(acc[mi][ni][2], acc[mi][ni][3]);
            }
        }
    }

    // fold per-column sums of this 128-row tile into g_vsum (v-slice only)
    if (dovs) {
        int b = m0 >> 11;                       // batch of this row tile
        #pragma unroll
        for (int ni = 0; ni < 4; ni++) {
            float c0s = 0.0f, c1s = 0.0f;
            #pragma unroll
            for (int mi = 0; mi < 4; mi++) {
                c0s += acc[mi][ni][0] + acc[mi][ni][2];
                c1s += acc[mi][ni][1] + acc[mi][ni][3];
            }
            #pragma unroll
            for (int o = 4; o < 32; o <<= 1) {
                c0s += __shfl_xor_sync(0xFFFFFFFFu, c0s, o);
                c1s += __shfl_xor_sync(0xFFFFFFFFu, c1s, o);
            }
            if (lrow == 0) {
                int cn = n0 + n_base + ni * 8 + lcol * 2;
                atomicAdd(&g_vsum[b * C + cn],     c0s);
                atomicAdd(&g_vsum[b * C + cn + 1], c1s);
            }
        }
    }
}

// ---------------- sparse masked attention v9: split lists ------------------
// Grid (E, 2): block (q, z) processes list entries {4z, 4z+8, ...} (4/iter).
// 128 threads = 2 batches x 64; thread owns 8 channels. z=0 seeds 0.5*vsum.
// Partials land in g_part0 / g_part1; the proj GEMM sums them on load.
__device__ __forceinline__ float hdot8(uint4 qr, uint4 kr) {
    const __half2* qh = reinterpret_cast<const __half2*>(&qr);
    const __half2* kh = reinterpret_cast<const __half2*>(&kr);
    __half2 p = __hmul2(qh[0], kh[0]);
    p = __hfma2(qh[1], kh[1], p);
    p = __hfma2(qh[2], kh[2], p);
    p = __hfma2(qh[3], kh[3], p);
    float2 pf = __half22float2(p);
    return pf.x + pf.y;
}

__global__ __launch_bounds__(128) void attn_sparse9()
{
    __shared__ float2 sp[CAP];

    int q   = blockIdx.x;
    int zz  = blockIdx.y;         // list half 0/1
    int tid = threadIdx.x;        // 0..127
    int bb  = tid >> 6;           // batch 0/1
    int t   = tid & 63;
    int c0  = t * 8;              // channel start (head = c0/64)

    int n    = g_cnt[q];
    int npad = (n + 3) & ~3;
    for (int i = tid; i < npad; i += 128)
        sp[i] = (i < n) ? g_pair[q * CAP + i] : make_float2(__int_as_float(0), 0.0f);
    __syncthreads();

    const __half* kvb = g_qkv16 + (size_t)bb * E * QC;

    uint4 qr = *reinterpret_cast<const uint4*>(kvb + (size_t)q * QC + c0);

    float acc[8];
    if (zz == 0) {
        float4 a = *reinterpret_cast<const float4*>(g_vsum + bb * C + c0);
        float4 b = *reinterpret_cast<const float4*>(g_vsum + bb * C + c0 + 4);
        acc[0] = 0.5f * a.x; acc[1] = 0.5f * a.y; acc[2] = 0.5f * a.z; acc[3] = 0.5f * a.w;
        acc[4] = 0.5f * b.x; acc[5] = 0.5f * b.y; acc[6] = 0.5f * b.z; acc[7] = 0.5f * b.w;
    } else {
        #pragma unroll
        for (int j = 0; j < 8; j++) acc[j] = 0.0f;
    }

    const __half* kb = kvb + 512 + c0;   // + rowoff -> k row; +512 more -> v

    for (int i = zz * 4; i < npad; i += 8) {
        float2 pr0 = sp[i], pr1 = sp[i + 1], pr2 = sp[i + 2], pr3 = sp[i + 3];
        const __half* r0 = kb + __float_as_int(pr0.x);
        const __half* r1 = kb + __float_as_int(pr1.x);
        const __half* r2 = kb + __float_as_int(pr2.x);
        const __half* r3 = kb + __float_as_int(pr3.x);

        uint4 kr0 = *reinterpret_cast<const uint4*>(r0);
        uint4 kr1 = *reinterpret_cast<const uint4*>(r1);
        uint4 kr2 = *reinterpret_cast<const uint4*>(r2);
        uint4 kr3 = *reinterpret_cast<const uint4*>(r3);
        uint4 vr0 = *reinterpret_cast<const uint4*>(r0 + 512);
        uint4 vr1 = *reinterpret_cast<const uint4*>(r1 + 512);
        uint4 vr2 = *reinterpret_cast<const uint4*>(r2 + 512);
        uint4 vr3 = *reinterpret_cast<const uint4*>(r3 + 512);

        float p0 = hdot8(qr, kr0);
        float p1 = hdot8(qr, kr1);
        float p2 = hdot8(qr, kr2);
        float p3 = hdot8(qr, kr3);

        #pragma unroll
        for (int o = 1; o < 8; o <<= 1) {
            p0 += __shfl_xor_sync(0xFFFFFFFFu, p0, o, 8);
            p1 += __shfl_xor_sync(0xFFFFFFFFu, p1, o, 8);
            p2 += __shfl_xor_sync(0xFFFFFFFFu, p2, o, 8);
            p3 += __shfl_xor_sync(0xFFFFFFFFu, p3, o, 8);
        }

        __half2 sh0 = __float2half2_rn(0.5f * pr0.y * p0);
        __half2 sh1 = __float2half2_rn(0.5f * pr1.y * p1);
        __half2 sh2 = __float2half2_rn(0.5f * pr2.y * p2);
        __half2 sh3 = __float2half2_rn(0.5f * pr3.y * p3);

        const __half2* v0h = reinterpret_cast<const __half2*>(&vr0);
        const __half2* v1h = reinterpret_cast<const __half2*>(&vr1);
        const __half2* v2h = reinterpret_cast<const __half2*>(&vr2);
        const __half2* v3h = reinterpret_cast<const __half2*>(&vr3);

        #pragma unroll
        for (int j = 0; j < 4; j++) {
            __half2 a = __hmul2(sh0, v0h[j]);
            a = __hfma2(sh1, v1h[j], a);
            a = __hfma2(sh2, v2h[j], a);
            a = __hfma2(sh3, v3h[j], a);
            float2 f = __half22float2(a);
            acc[2 * j]     += f.x;
            acc[2 * j + 1] += f.y;
        }
    }

    uint4 outp;
    __half2* hp = reinterpret_cast<__half2*>(&outp);
    hp[0] = __floats2half2_rn(acc[0], acc[1]);
    hp[1] = __floats2half2_rn(acc[2], acc[3]);
    hp[2] = __floats2half2_rn(acc[4], acc[5]);
    hp[3] = __floats2half2_rn(acc[6], acc[7]);
    __half* dst = zz ? g_part1 : g_part0;
    *reinterpret_cast<uint4*>(dst + ((size_t)(bb * E + q)) * C + c0) = outp;
}

// ---------------- bias + LayerNorm + residual (float4, 2 partials) ---------
__global__ __launch_bounds__(128) void ln_residual(
    const float* __restrict__ x,  const float* __restrict__ bp,
    const float* __restrict__ w,  const float* __restrict__ bb,
    const float* __restrict__ gamma, float* __restrict__ out)
{
    int row = blockIdx.x;          // 0..4095
    int tid = threadIdx.x;         // 128; thread owns 4 consecutive channels
    int c   = tid * 4;

    float4 y  = *reinterpret_cast<const float4*>(g_p  + (size_t)row * C + c);
    float4 y2 = *reinterpret_cast<const float4*>(g_p2 + (size_t)row * C + c);
    float4 bv = *reinterpret_cast<const float4*>(bp + c);
    y.x += y2.x + bv.x; y.y += y2.y + bv.y;
    y.z += y2.z + bv.z; y.w += y2.w + bv.w;

    float sum = y.x + y.y + y.z + y.w;
    float sq  = y.x * y.x + y.y * y.y + y.z * y.z + y.w * y.w;

    #pragma unroll
    for (int o = 16; o; o >>= 1) {
        sum += __shfl_xor_sync(0xFFFFFFFFu, sum, o);
        sq  += __shfl_xor_sync(0xFFFFFFFFu, sq,  o);
    }
    __shared__ float s1[4], s2[4];
    int wid = tid >> 5, lane = tid & 31;
    if (lane == 0) { s1[wid] = sum; s2[wid] = sq; }
    __syncthreads();
    float tot  = s1[0] + s1[1] + s1[2] + s1[3];
    float totq = s2[0] + s2[1] + s2[2] + s2[3];

    float mu  = tot * (1.0f / C);
    float var = totq * (1.0f / C) - mu * mu;
    float rs  = rsqrtf(var + 1e-5f);
    float gm  = gamma[0];

    float4 wv = *reinterpret_cast<const float4*>(w + c);
    float4 bbv = *reinterpret_cast<const float4*>(bb + c);
    float4 xv = *reinterpret_cast<const float4*>(x + (size_t)row * C + c);
    float4 o;
    o.x = xv.x + gm * ((y.x - mu) * rs * wv.x + bbv.x);
    o.y = xv.y + gm * ((y.y - mu) * rs * wv.y + bbv.y);
    o.z = xv.z + gm * ((y.z - mu) * rs * wv.z + bbv.z);
    o.w = xv.w + gm * ((y.w - mu) * rs * wv.w + bbv.w);
    *reinterpret_cast<float4*>(out + (size_t)row * C + c) = o;
}

// ---------------- launch ----------------------------------------------------
extern "C" void kernel_launch(void* const* d_in, const int* in_sizes, int n_in,
                              void* d_out, int out_size)
{
    const float* x     = (const float*)d_in[0];
    const float* mask  = (const float*)d_in[1];
    const float* Wq    = (const float*)d_in[2];
    const float* Wk    = (const float*)d_in[3];
    const float* Wv    = (const float*)d_in[4];
    const float* Wp    = (const float*)d_in[5];
    const float* bp    = (const float*)d_in[6];
    const float* lnw   = (const float*)d_in[7];
    const float* lnb   = (const float*)d_in[8];
    const float* gamma = (const float*)d_in[9];
    float* out = (float*)d_out;

    __half *x16p, *w16p, *qkv16p, *p0p, *p1p;
    float *pp;
    cudaGetSymbolAddress((void**)&x16p, g_x16);
    cudaGetSymbolAddress((void**)&w16p, g_w16);
    cudaGetSymbolAddress((void**)&qkv16p, g_qkv16);
    cudaGetSymbolAddress((void**)&p0p, g_part0);
    cudaGetSymbolAddress((void**)&p1p, g_part1);
    cudaGetSymbolAddress((void**)&pp, g_p);   // g_p and g_p2 are adjacent via z offset

    // 0) fused: convert x/W to fp16 + zero vsum + mask CSR compaction
    conv_and_csr<<<NCONV + E / 8, 256>>>(x, Wq, Wk, Wv, Wp, mask);

    // 1) fused QKV projection -> g_qkv16 (fp16); v-slice also folds g_vsum
    gemm_f16<true, false, 1><<<dim3(C / GN, M_TOT / GM, 3), 256>>>(
        x16p, nullptr, w16p, w16p + C * C, w16p + 2 * C * C, qkv16p, QC, 512);

    // 2) sparse masked attention, list split across 2 blocks -> g_part0/1
    attn_sparse9<<<dim3(E, 2), 128>>>();

    // 3) output projection, split-K=2 (A = part0 + part1 fused) -> g_p, g_p2
    //    NOTE: z=1 output goes to g_p + M_TOT*C which must be g_p2; both are
    //    device globals — pass g_p's address and rely on the z offset only if
    //    they are contiguous. They may not be, so launch per-half explicitly.
    {
        float *pp2;
        cudaGetSymbolAddress((void**)&pp2, g_p2);
        // two z-slices in one grid would need contiguity; instead use the
        // KSPLIT template with explicit per-half grids (still concurrent-free
        // but each is 128 CTAs; keep one grid by passing base pointers):
        // simplest correct approach: one launch with z in {0,1}, where the
        // kernel indexes Cout + z*M_TOT*C. Guarantee contiguity by writing
        // both halves through a single symbol: g_p is used for z=0 and g_p2
        // for z=1 via separate launches to stay safe.
        gemm_f16<false, true, 2><<<dim3(C / GN, M_TOT / GM, 1), 256>>>(
            p0p, p1p, w16p + 3 * C * C, w16p + 3 * C * C, w16p + 3 * C * C, pp, C, 0);
        // second half: shift A/B by koff manually via template z=1 path —
        // emulate by launching with gridDim.z=1 and pointer offsets:
        gemm_f16<false, true, 2><<<dim3(C / GN, M_TOT / GM, 1), 256>>>(
            p0p + 256, p1p + 256, w16p + 3 * C * C + 256,
            w16p + 3 * C * C + 256, w16p + 3 * C * C + 256, pp2, C, 0);
    }

    // 4) bias + LN + residual (sums the two proj partials)
    ln_residual<<<M_TOT, 128>>>(x, bp, lnw, lnb, gamma, out);
}

// round 16
// speedup vs baseline: 1.0451x; 1.0451x over previous
#include <cuda_runtime.h>
#include <cuda_fp16.h>

// Problem constants
#define Bsz 2
#define E 2048
#define C 512
#define H 8
#define D 64
#define M_TOT (Bsz * E)       // 4096
#define CAP 320               // per-row nnz capacity (mean ~102)
#define QC 1536               // fused q|k|v half row length

// ---------------- scratch (device globals; no allocation) ----------------
__device__ __half  g_x16[M_TOT * C];        // x in fp16
__device__ __half  g_w16[4 * C * C];        // Wq|Wk|Wv|Wp in fp16
__device__ __half  g_qkv16[M_TOT * QC];     // [row][ q | k | v ] fp16
__device__ __half  g_part0[M_TOT * C];      // attention partial 0 (fp16)
__device__ __half  g_part1[M_TOT * C];      // attention partial 1 (fp16)
__device__ float   g_p[2 * M_TOT * C];      // proj split-K partials (fp32, contiguous)
__device__ int     g_cnt[E];
__device__ float2  g_pair[E * CAP];         // (rowoffset-as-bits, maskval)
__device__ float   g_vsum[Bsz * C];

// ---------------- fused: fp32->fp16 conversion + mask CSR + vsum zero -----
// Blocks [0, NCONV): convert x and the 4 weight matrices to fp16.
// Blocks [NCONV, NCONV + E/8): mask -> per-row (rowoff,val) pair lists,
// warp per row (8 rows per 256-thread block), ballot compaction.
#define NCONV ((M_TOT * C + 4 * C * C) / 4 / 256)   // 3072

__global__ __launch_bounds__(256) void conv_and_csr(
    const float* __restrict__ x,
    const float* __restrict__ Wq, const float* __restrict__ Wk,
    const float* __restrict__ Wv, const float* __restrict__ Wp,
    const float* __restrict__ mask)
{
    if (blockIdx.x < NCONV) {
        if (blockIdx.x == 0) {   // also zero the vsum accumulator (1024 floats)
            *reinterpret_cast<float4*>(g_vsum + threadIdx.x * 4) =
                make_float4(0.f, 0.f, 0.f, 0.f);
        }
        int idx = (blockIdx.x * 256 + threadIdx.x) * 4;   // float4 granularity
        const int NX = M_TOT * C;                          // 2^21
        const float* src;
        __half* dst;
        if (idx < NX) {
            src = x + idx;
            dst = g_x16 + idx;
        } else {
            int j = idx - NX;                              // [0, 2^20)
            int region = j >> 18;
            int off = j & ((C * C) - 1);
            src = (region == 0 ? Wq : region == 1 ? Wk : region == 2 ? Wv : Wp) + off;
            dst = g_w16 + j;
        }
        float4 f = *reinterpret_cast<const float4*>(src);
        *reinterpret_cast<__half2*>(dst)     = __floats2half2_rn(f.x, f.y);
        *reinterpret_cast<__half2*>(dst + 2) = __floats2half2_rn(f.z, f.w);
        return;
    }

    // ---- CSR part: warp per row ----
    int row  = (blockIdx.x - NCONV) * 8 + (threadIdx.x >> 5);
    int lane = threadIdx.x & 31;

    int cnt = 0;
    const float* mrow = mask + (size_t)row * E;
    float2* prow = g_pair + row * CAP;
    unsigned below = (1u << lane) - 1u;

    float4 v = *reinterpret_cast<const float4*>(mrow + lane * 4);
    for (int j0 = 0; j0 < E; j0 += 128) {
        float4 nv;
        if (j0 + 128 < E)
            nv = *reinterpret_cast<const float4*>(mrow + j0 + 128 + lane * 4);

        unsigned b0 = __ballot_sync(0xFFFFFFFFu, v.x != 0.0f);
        unsigned b1 = __ballot_sync(0xFFFFFFFFu, v.y != 0.0f);
        unsigned b2 = __ballot_sync(0xFFFFFFFFu, v.z != 0.0f);
        unsigned b3 = __ballot_sync(0xFFFFFFFFu, v.w != 0.0f);
        int t0 = __popc(b0), t1 = __popc(b1), t2 = __popc(b2), t3 = __popc(b3);
        int jb = (j0 + lane * 4) * QC;

        if (v.x != 0.0f) {
            int o = cnt + __popc(b0 & below);
            if (o < CAP) prow[o] = make_float2(__int_as_float(jb), v.x);
        }
        if (v.y != 0.0f) {
            int o = cnt + t0 + __popc(b1 & below);
            if (o < CAP) prow[o] = make_float2(__int_as_float(jb + QC), v.y);
        }
        if (v.z != 0.0f) {
            int o = cnt + t0 + t1 + __popc(b2 & below);
            if (o < CAP) prow[o] = make_float2(__int_as_float(jb + 2 * QC), v.z);
        }
        if (v.w != 0.0f) {
            int o = cnt + t0 + t1 + t2 + __popc(b3 & below);
            if (o < CAP) prow[o] = make_float2(__int_as_float(jb + 3 * QC), v.w);
        }
        cnt += t0 + t1 + t2 + t3;
        v = nv;
    }
    if (lane == 0) g_cnt[row] = (cnt > CAP) ? CAP : cnt;
}

// =============== fp16 tensor-core GEMM (ldmatrix frag loads) ==============
// C[m, coloff+n] = sum_k A[m,k]*B[n,k].  128x128x32 tiles, double-buffered,
// 256 threads = 8 warps (2m x 4n), warp tile 64x32, mma m16n8k16 f16->f32.
// ADD_A: A operand = half-sum of A and A2 (attention partials combiner).
// KSPLIT>1: blockIdx.z selects k-range [z*C/KSPLIT, ...) and output partial
// buffer Cout + z*M_TOT*C floats (B is B0 for all z). KSPLIT==1 QKV path:
// z selects B0/B1/B2 + column offset; z==2 (v-slice) folds g_vsum.
#define GM 128
#define GN 128
#define GKH 32     // k-halves per tile
#define SAH 40     // padded row stride in halves (80B -> conflict-free LDSM)

__device__ __forceinline__ void mma_f16(float* c, const unsigned* a, const unsigned* b) {
    asm volatile(
        "mma.sync.aligned.m16n8k16.row.col.f32.f16.f16.f32 "
        "{%0,%1,%2,%3}, {%4,%5,%6,%7}, {%8,%9}, {%0,%1,%2,%3};\n"
        : "+f"(c[0]), "+f"(c[1]), "+f"(c[2]), "+f"(c[3])
        : "r"(a[0]), "r"(a[1]), "r"(a[2]), "r"(a[3]), "r"(b[0]), "r"(b[1]));
}

__device__ __forceinline__ void ldsm_x4(unsigned* r, const __half* p) {
    unsigned a = (unsigned)__cvta_generic_to_shared(p);
    asm volatile(
        "ldmatrix.sync.aligned.m8n8.x4.shared.b16 {%0,%1,%2,%3}, [%4];\n"
        : "=r"(r[0]), "=r"(r[1]), "=r"(r[2]), "=r"(r[3]) : "r"(a));
}

__device__ __forceinline__ uint4 hadd8(uint4 a, uint4 b) {
    uint4 r;
    *reinterpret_cast<__half2*>(&r.x) = __hadd2(
        *reinterpret_cast<__half2*>(&a.x), *reinterpret_cast<__half2*>(&b.x));
    *reinterpret_cast<__half2*>(&r.y) = __hadd2(
        *reinterpret_cast<__half2*>(&a.y), *reinterpret_cast<__half2*>(&b.y));
    *reinterpret_cast<__half2*>(&r.z) = __hadd2(
        *reinterpret_cast<__half2*>(&a.z), *reinterpret_cast<__half2*>(&b.z));
    *reinterpret_cast<__half2*>(&r.w) = __hadd2(
        *reinterpret_cast<__half2*>(&a.w), *reinterpret_cast<__half2*>(&b.w));
    return r;
}

template <bool HALF_OUT, bool ADD_A, int KSPLIT>
__global__ __launch_bounds__(256) void gemm_f16(
    const __half* __restrict__ A, const __half* __restrict__ A2,
    const __half* __restrict__ B0, const __half* __restrict__ B1,
    const __half* __restrict__ B2,
    void* __restrict__ Cout, int ldc, int coloff_mul)
{
    int z = blockIdx.z;
    const __half* Bm = (KSPLIT > 1) ? B0 : ((z == 0) ? B0 : (z == 1 ? B1 : B2));
    int coloff = (KSPLIT > 1) ? 0 : z * coloff_mul;
    int koff   = (KSPLIT > 1) ? z * (C / KSPLIT) : 0;
    bool dovs = (KSPLIT == 1) && (coloff_mul != 0) && (z == 2);

    __shared__ __align__(16) __half As[2][GM][SAH];
    __shared__ __align__(16) __half Bs[2][GN][SAH];

    int tid  = threadIdx.x;
    int lane = tid & 31;
    int warp = tid >> 5;
    int m0 = blockIdx.y * GM;
    int n0 = blockIdx.x * GN;

    int lr = tid >> 1;
    int lc = (tid & 1) * 16;
    size_t aoff = (size_t)(m0 + lr) * C + lc + koff;
    const __half* Ag  = A + aoff;
    const __half* Ag2 = ADD_A ? (A2 + aoff) : nullptr;
    const __half* Bg  = Bm + (size_t)(n0 + lr) * C + lc + koff;

    int m_base = (warp >> 2) * 64;
    int n_base = (warp & 3) * 32;
    int lrow = lane >> 2;
    int lcol = lane & 3;

    // ldmatrix per-lane row/col components
    int a_row = m_base + (lane & 15);        // + mi*16
    int a_k   = (lane >> 4) * 8;             // + ks*16
    int b_row = n_base + (lane >> 4) * 8 + (lane & 7);   // + nip*16
    int b_k   = ((lane >> 3) & 1) * 8;       // + ks*16

    float acc[4][4][4];
    #pragma unroll
    for (int mi = 0; mi < 4; mi++)
        #pragma unroll
        for (int ni = 0; ni < 4; ni++)
            #pragma unroll
            for (int r = 0; r < 4; r++) acc[mi][ni][r] = 0.0f;

    const int nt = C / GKH / KSPLIT;   // 16 (KSPLIT=1) or 8 (KSPLIT=2)

    uint4 pa0, pa1, pb0, pb1;
    pa0 = *reinterpret_cast<const uint4*>(Ag);
    pa1 = *reinterpret_cast<const uint4*>(Ag + 8);
    if (ADD_A) {
        pa0 = hadd8(pa0, *reinterpret_cast<const uint4*>(Ag2));
        pa1 = hadd8(pa1, *reinterpret_cast<const uint4*>(Ag2 + 8));
    }
    pb0 = *reinterpret_cast<const uint4*>(Bg);
    pb1 = *reinterpret_cast<const uint4*>(Bg + 8);

    *reinterpret_cast<uint4*>(&As[0][lr][lc])     = pa0;
    *reinterpret_cast<uint4*>(&As[0][lr][lc + 8]) = pa1;
    *reinterpret_cast<uint4*>(&Bs[0][lr][lc])     = pb0;
    *reinterpret_cast<uint4*>(&Bs[0][lr][lc + 8]) = pb1;
    __syncthreads();

    for (int kt = 0; kt < nt; kt++) {
        int cur = kt & 1;
        bool more = (kt + 1) < nt;
        if (more) {
            const __half* Ap = Ag + (kt + 1) * GKH;
            const __half* Bp = Bg + (kt + 1) * GKH;
            pa0 = *reinterpret_cast<const uint4*>(Ap);
            pa1 = *reinterpret_cast<const uint4*>(Ap + 8);
            if (ADD_A) {
                const __half* Ap2 = Ag2 + (kt + 1) * GKH;
                pa0 = hadd8(pa0, *reinterpret_cast<const uint4*>(Ap2));
                pa1 = hadd8(pa1, *reinterpret_cast<const uint4*>(Ap2 + 8));
            }
            pb0 = *reinterpret_cast<const uint4*>(Bp);
            pb1 = *reinterpret_cast<const uint4*>(Bp + 8);
        }

        #pragma unroll
        for (int ks = 0; ks < 2; ks++) {
            unsigned afr[4][4];
            #pragma unroll
            for (int mi = 0; mi < 4; mi++)
                ldsm_x4(afr[mi], &As[cur][a_row + mi * 16][ks * 16 + a_k]);
            unsigned bfr[4][2];
            #pragma unroll
            for (int nip = 0; nip < 2; nip++) {
                unsigned t[4];
                ldsm_x4(t, &Bs[cur][b_row + nip * 16][ks * 16 + b_k]);
                bfr[nip * 2][0]     = t[0];
                bfr[nip * 2][1]     = t[1];
                bfr[nip * 2 + 1][0] = t[2];
                bfr[nip * 2 + 1][1] = t[3];
            }
            #pragma unroll
            for (int mi = 0; mi < 4; mi++)
                #pragma unroll
                for (int ni = 0; ni < 4; ni++)
                    mma_f16(acc[mi][ni], afr[mi], bfr[ni]);
        }

        if (more) {
            int nxt = cur ^ 1;
            *reinterpret_cast<uint4*>(&As[nxt][lr][lc])     = pa0;
            *reinterpret_cast<uint4*>(&As[nxt][lr][lc + 8]) = pa1;
            *reinterpret_cast<uint4*>(&Bs[nxt][lr][lc])     = pb0;
            *reinterpret_cast<uint4*>(&Bs[nxt][lr][lc + 8]) = pb1;
            __syncthreads();
        }
    }

    float* Cf = (float*)Cout + ((KSPLIT > 1) ? (size_t)z * M_TOT * C : 0);
    #pragma unroll
    for (int mi = 0; mi < 4; mi++) {
        #pragma unroll
        for (int ni = 0; ni < 4; ni++) {
            int r  = m0 + m_base + mi * 16 + lrow;
            int cc = coloff + n0 + n_base + ni * 8 + lcol * 2;
            if (HALF_OUT) {
                __half* Ch = (__half*)Cout;
                *reinterpret_cast<__half2*>(Ch + (size_t)r * ldc + cc) =
                    __floats2half2_rn(acc[mi][ni][0], acc[mi][ni][1]);
                *reinterpret_cast<__half2*>(Ch + (size_t)(r + 8) * ldc + cc) =
                    __floats2half2_rn(acc[mi][ni][2], acc[mi][ni][3]);
            } else {
                *reinterpret_cast<float2*>(Cf + (size_t)r * ldc + cc) =
                    make_float2(acc[mi][ni][0], acc[mi][ni][1]);
                *reinterpret_cast<float2*>(Cf + (size_t)(r + 8) * ldc + cc) =
                    make_float2(acc[mi][ni][2], acc[mi][ni][3]);
            }
        }
    }

    // fold per-column sums of this 128-row tile into g_vsum (v-slice only)
    if (dovs) {
        int b = m0 >> 11;                       // batch of this row tile
        #pragma unroll
        for (int ni = 0; ni < 4; ni++) {
            float c0s = 0.0f, c1s = 0.0f;
            #pragma unroll
            for (int mi = 0; mi < 4; mi++) {
                c0s += acc[mi][ni][0] + acc[mi][ni][2];
                c1s += acc[mi][ni][1] + acc[mi][ni][3];
            }
            #pragma unroll
            for (int o = 4; o < 32; o <<= 1) {
                c0s += __shfl_xor_sync(0xFFFFFFFFu, c0s, o);
                c1s += __shfl_xor_sync(0xFFFFFFFFu, c1s, o);
            }
            if (lrow == 0) {
                int cn = n0 + n_base + ni * 8 + lcol * 2;
                atomicAdd(&g_vsum[b * C + cn],     c0s);
                atomicAdd(&g_vsum[b * C + cn + 1], c1s);
            }
        }
    }
}

// ---------------- sparse masked attention v9: split lists ------------------
// Grid (E, 2): block (q, z) processes list entries {4z, 4z+8, ...} (4/iter).
// 128 threads = 2 batches x 64; thread owns 8 channels. z=0 seeds 0.5*vsum.
// Partials land in g_part0 / g_part1; the proj GEMM sums them on load.
__device__ __forceinline__ float hdot8(uint4 qr, uint4 kr) {
    const __half2* qh = reinterpret_cast<const __half2*>(&qr);
    const __half2* kh = reinterpret_cast<const __half2*>(&kr);
    __half2 p = __hmul2(qh[0], kh[0]);
    p = __hfma2(qh[1], kh[1], p);
    p = __hfma2(qh[2], kh[2], p);
    p = __hfma2(qh[3], kh[3], p);
    float2 pf = __half22float2(p);
    return pf.x + pf.y;
}

__global__ __launch_bounds__(128) void attn_sparse9()
{
    __shared__ float2 sp[CAP];

    int q   = blockIdx.x;
    int zz  = blockIdx.y;         // list half 0/1
    int tid = threadIdx.x;        // 0..127
    int bb  = tid >> 6;           // batch 0/1
    int t   = tid & 63;
    int c0  = t * 8;              // channel start (head = c0/64)

    int n    = g_cnt[q];
    int npad = (n + 3) & ~3;
    for (int i = tid; i < npad; i += 128)
        sp[i] = (i < n) ? g_pair[q * CAP + i] : make_float2(__int_as_float(0), 0.0f);
    __syncthreads();

    const __half* kvb = g_qkv16 + (size_t)bb * E * QC;

    uint4 qr = *reinterpret_cast<const uint4*>(kvb + (size_t)q * QC + c0);

    float acc[8];
    if (zz == 0) {
        float4 a = *reinterpret_cast<const float4*>(g_vsum + bb * C + c0);
        float4 b = *reinterpret_cast<const float4*>(g_vsum + bb * C + c0 + 4);
        acc[0] = 0.5f * a.x; acc[1] = 0.5f * a.y; acc[2] = 0.5f * a.z; acc[3] = 0.5f * a.w;
        acc[4] = 0.5f * b.x; acc[5] = 0.5f * b.y; acc[6] = 0.5f * b.z; acc[7] = 0.5f * b.w;
    } else {
        #pragma unroll
        for (int j = 0; j < 8; j++) acc[j] = 0.0f;
    }

    const __half* kb = kvb + 512 + c0;   // + rowoff -> k row; +512 more -> v

    for (int i = zz * 4; i < npad; i += 8) {
        float2 pr0 = sp[i], pr1 = sp[i + 1], pr2 = sp[i + 2], pr3 = sp[i + 3];
        const __half* r0 = kb + __float_as_int(pr0.x);
        const __half* r1 = kb + __float_as_int(pr1.x);
        const __half* r2 = kb + __float_as_int(pr2.x);
        const __half* r3 = kb + __float_as_int(pr3.x);

        uint4 kr0 = *reinterpret_cast<const uint4*>(r0);
        uint4 kr1 = *reinterpret_cast<const uint4*>(r1);
        uint4 kr2 = *reinterpret_cast<const uint4*>(r2);
        uint4 kr3 = *reinterpret_cast<const uint4*>(r3);
        uint4 vr0 = *reinterpret_cast<const uint4*>(r0 + 512);
        uint4 vr1 = *reinterpret_cast<const uint4*>(r1 + 512);
        uint4 vr2 = *reinterpret_cast<const uint4*>(r2 + 512);
        uint4 vr3 = *reinterpret_cast<const uint4*>(r3 + 512);

        float p0 = hdot8(qr, kr0);
        float p1 = hdot8(qr, kr1);
        float p2 = hdot8(qr, kr2);
        float p3 = hdot8(qr, kr3);

        #pragma unroll
        for (int o = 1; o < 8; o <<= 1) {
            p0 += __shfl_xor_sync(0xFFFFFFFFu, p0, o, 8);
            p1 += __shfl_xor_sync(0xFFFFFFFFu, p1, o, 8);
            p2 += __shfl_xor_sync(0xFFFFFFFFu, p2, o, 8);
            p3 += __shfl_xor_sync(0xFFFFFFFFu, p3, o, 8);
        }

        __half2 sh0 = __float2half2_rn(0.5f * pr0.y * p0);
        __half2 sh1 = __float2half2_rn(0.5f * pr1.y * p1);
        __half2 sh2 = __float2half2_rn(0.5f * pr2.y * p2);
        __half2 sh3 = __float2half2_rn(0.5f * pr3.y * p3);

        const __half2* v0h = reinterpret_cast<const __half2*>(&vr0);
        const __half2* v1h = reinterpret_cast<const __half2*>(&vr1);
        const __half2* v2h = reinterpret_cast<const __half2*>(&vr2);
        const __half2* v3h = reinterpret_cast<const __half2*>(&vr3);

        #pragma unroll
        for (int j = 0; j < 4; j++) {
            __half2 a = __hmul2(sh0, v0h[j]);
            a = __hfma2(sh1, v1h[j], a);
            a = __hfma2(sh2, v2h[j], a);
            a = __hfma2(sh3, v3h[j], a);
            float2 f = __half22float2(a);
            acc[2 * j]     += f.x;
            acc[2 * j + 1] += f.y;
        }
    }

    uint4 outp;
    __half2* hp = reinterpret_cast<__half2*>(&outp);
    hp[0] = __floats2half2_rn(acc[0], acc[1]);
    hp[1] = __floats2half2_rn(acc[2], acc[3]);
    hp[2] = __floats2half2_rn(acc[4], acc[5]);
    hp[3] = __floats2half2_rn(acc[6], acc[7]);
    __half* dst = zz ? g_part1 : g_part0;
    *reinterpret_cast<uint4*>(dst + ((size_t)(bb * E + q)) * C + c0) = outp;
}

// ---------------- bias + LayerNorm + residual (float4, 2 partials) ---------
__global__ __launch_bounds__(128) void ln_residual(
    const float* __restrict__ x,  const float* __restrict__ bp,
    const float* __restrict__ w,  const float* __restrict__ bb,
    const float* __restrict__ gamma, float* __restrict__ out)
{
    int row = blockIdx.x;          // 0..4095
    int tid = threadIdx.x;         // 128; thread owns 4 consecutive channels
    int c   = tid * 4;

    float4 y  = *reinterpret_cast<const float4*>(g_p + (size_t)row * C + c);
    float4 y2 = *reinterpret_cast<const float4*>(g_p + (size_t)M_TOT * C
                                                     + (size_t)row * C + c);
    float4 bv = *reinterpret_cast<const float4*>(bp + c);
    y.x += y2.x + bv.x; y.y += y2.y + bv.y;
    y.z += y2.z + bv.z; y.w += y2.w + bv.w;

    float sum = y.x + y.y + y.z + y.w;
    float sq  = y.x * y.x + y.y * y.y + y.z * y.z + y.w * y.w;

    #pragma unroll
    for (int o = 16; o; o >>= 1) {
        sum += __shfl_xor_sync(0xFFFFFFFFu, sum, o);
        sq  += __shfl_xor_sync(0xFFFFFFFFu, sq,  o);
    }
    __shared__ float s1[4], s2[4];
    int wid = tid >> 5, lane = tid & 31;
    if (lane == 0) { s1[wid] = sum; s2[wid] = sq; }
    __syncthreads();
    float tot  = s1[0] + s1[1] + s1[2] + s1[3];
    float totq = s2[0] + s2[1] + s2[2] + s2[3];

    float mu  = tot * (1.0f / C);
    float var = totq * (1.0f / C) - mu * mu;
    float rs  = rsqrtf(var + 1e-5f);
    float gm  = gamma[0];

    float4 wv = *reinterpret_cast<const float4*>(w + c);
    float4 bbv = *reinterpret_cast<const float4*>(bb + c);
    float4 xv = *reinterpret_cast<const float4*>(x + (size_t)row * C + c);
    float4 o;
    o.x = xv.x + gm * ((y.x - mu) * rs * wv.x + bbv.x);
    o.y = xv.y + gm * ((y.y - mu) * rs * wv.y + bbv.y);
    o.z = xv.z + gm * ((y.z - mu) * rs * wv.z + bbv.z);
    o.w = xv.w + gm * ((y.w - mu) * rs * wv.w + bbv.w);
    *reinterpret_cast<float4*>(out + (size_t)row * C + c) = o;
}

// ---------------- launch ----------------------------------------------------
extern "C" void kernel_launch(void* const* d_in, const int* in_sizes, int n_in,
                              void* d_out, int out_size)
{
    const float* x     = (const float*)d_in[0];
    const float* mask  = (const float*)d_in[1];
    const float* Wq    = (const float*)d_in[2];
    const float* Wk    = (const float*)d_in[3];
    const float* Wv    = (const float*)d_in[4];
    const float* Wp    = (const float*)d_in[5];
    const float* bp    = (const float*)d_in[6];
    const float* lnw   = (const float*)d_in[7];
    const float* lnb   = (const float*)d_in[8];
    const float* gamma = (const float*)d_in[9];
    float* out = (float*)d_out;

    __half *x16p, *w16p, *qkv16p, *p0p, *p1p;
    float *pp;
    cudaGetSymbolAddress((void**)&x16p, g_x16);
    cudaGetSymbolAddress((void**)&w16p, g_w16);
    cudaGetSymbolAddress((void**)&qkv16p, g_qkv16);
    cudaGetSymbolAddress((void**)&p0p, g_part0);
    cudaGetSymbolAddress((void**)&p1p, g_part1);
    cudaGetSymbolAddress((void**)&pp, g_p);   // 2*M_TOT*C floats, contiguous

    // 0) fused: convert x/W to fp16 + zero vsum + mask CSR compaction
    conv_and_csr<<<NCONV + E / 8, 256>>>(x, Wq, Wk, Wv, Wp, mask);

    // 1) fused QKV projection -> g_qkv16 (fp16); v-slice also folds g_vsum
    gemm_f16<true, false, 1><<<dim3(C / GN, M_TOT / GM, 3), 256>>>(
        x16p, nullptr, w16p, w16p + C * C, w16p + 2 * C * C, qkv16p, QC, 512);

    // 2) sparse masked attention, list split across 2 blocks -> g_part0/1
    attn_sparse9<<<dim3(E, 2), 128>>>();

    // 3) output projection, split-K=2 in ONE grid (z = k-half) -> g_p[2 halves]
    gemm_f16<false, true, 2><<<dim3(C / GN, M_TOT / GM, 2), 256>>>(
        p0p, p1p, w16p + 3 * C * C, w16p + 3 * C * C, w16p + 3 * C * C, pp, C, 0);

    // 4) bias + LN + residual (sums the two proj partials)
    ln_residual<<<M_TOT, 128>>>(x, bp, lnw, lnb, gamma, out);
}